// round 11
// baseline (speedup 1.0000x reference)
#include <cuda_runtime.h>
#include <cstdint>

// B=4096 poses x N=4096 points, pure HBM streaming reduction (201 MB).
// R11: champion skeleton (warp-per-pose, 4096 one-warp CTAs, cap 28 = single
// wave, dist-2 prefetch, rsqrt norm, pointer-increment) + issue-mix tuning:
// float count accumulator (alu -> fma pipe), unroll 3.

#define NPTS 4096

__device__ __forceinline__ void process4(
    const float4 A, const float4 Bv, const float4 C,
    const float r00, const float r01, const float r02,
    const float r10, const float r11, const float r12,
    const float r20, const float r21, const float r22,
    const float trx, const float try_, const float trz,
    float& sum, float& cntf)
{
    // AABB bounds (identical double->float rounding to the numpy reference)
    const float lox = (float)(-0.001782 - (0.204416 / 2.0 + 0.001));
    const float hix = (float)(-0.001782 + (0.204416 / 2.0 + 0.001));
    const float loy = (float)(1.005e-05 - (0.0632517 / 2.0 + 0.001));
    const float hiy = (float)(1.005e-05 + (0.0632517 / 2.0 + 0.001));
    const float loz = (float)(0.0431621 - (0.1381738 / 2.0 + 0.001));
    const float hiz = (float)(0.0431621 + (0.1381738 / 2.0 + 0.001));

    const float px[4] = {A.x, A.w, Bv.z, C.y};
    const float py[4] = {A.y, Bv.x, Bv.w, C.z};
    const float pz[4] = {A.z, Bv.y, C.x, C.w};
#pragma unroll
    for (int k = 0; k < 4; ++k) {
        const float x = px[k], y = py[k], z = pz[k];
        const float rx = fmaf(r00, x, fmaf(r01, y, fmaf(r02, z, -trx)));
        const float ry = fmaf(r10, x, fmaf(r11, y, fmaf(r12, z, -try_)));
        const float rz = fmaf(r20, x, fmaf(r21, y, fmaf(r22, z, -trz)));
        const bool inside =
            (rx >= lox) & (rx <= hix) &
            (ry >= loy) & (ry <= hiy) &
            (rz >= loz) & (rz <= hiz);
        const float r2 = fmaf(rx, rx, fmaf(ry, ry, rz * rz));
        const float nrm = r2 * rsqrtf(fmaxf(r2, 1e-12f));  // = sqrt(r2)
        sum  += inside ? nrm : 0.0f;    // FSEL + FADD (fma pipe)
        cntf += inside ? 1.0f : 0.0f;   // FSEL + FADD (fma pipe, exact <= 2^24)
    }
}

__global__ __launch_bounds__(32, 28) void collision_dist_kernel(
    const float* __restrict__ trans,   // [B,3]
    const float* __restrict__ quat,    // [B,4]
    const float* __restrict__ pc,      // [B,N,3]
    float* __restrict__ out)           // [B,1]
{
    const int lane = threadIdx.x;
    const int b    = blockIdx.x;       // one pose per warp/CTA

    // per-lane base pointer; advances by constant stride -> LDG [R+imm]
    const float4* p = reinterpret_cast<const float4*>(
        pc + (size_t)b * (size_t)NPTS * 3) + (size_t)lane * 3;

    // ---- prologue: 2 chunks (6 float4) in flight before dependent math ----
    float4 buf[2][3];
    buf[0][0] = __ldcs(p + 0);  buf[0][1] = __ldcs(p + 1);  buf[0][2] = __ldcs(p + 2);
    buf[1][0] = __ldcs(p + 96); buf[1][1] = __ldcs(p + 97); buf[1][2] = __ldcs(p + 98);

    // ---- per-pose setup overlaps the in-flight loads ----
    const float qx = __ldg(&quat[b * 4 + 0]);
    const float qy = __ldg(&quat[b * 4 + 1]);
    const float qz = __ldg(&quat[b * 4 + 2]);
    const float qw = __ldg(&quat[b * 4 + 3]);
    const float inv = 1.0f / (qx * qx + qy * qy + qz * qz + qw * qw);
    const float tx = -qx * inv, ty = -qy * inv, tz = -qz * inv, tw = qw * inv;

    const float txx = tx * tx, tyy = ty * ty, tzz = tz * tz, tww = tw * tw;
    const float r00 = tww + txx - tyy - tzz;
    const float r11 = tww - txx + tyy - tzz;
    const float r22 = tww - txx - tyy + tzz;
    const float r01 = 2.0f * (tx * ty - tw * tz);
    const float r02 = 2.0f * (tx * tz + tw * ty);
    const float r10 = 2.0f * (tx * ty + tw * tz);
    const float r12 = 2.0f * (ty * tz - tw * tx);
    const float r20 = 2.0f * (tx * tz - tw * ty);
    const float r21 = 2.0f * (ty * tz + tw * tx);

    const float trx  = __ldg(&trans[b * 3 + 0]);
    const float try_ = __ldg(&trans[b * 3 + 1]);
    const float trz  = __ldg(&trans[b * 3 + 2]);

    // ---- steady state: 32 chunks/lane, distance-2, pointer-increment ----
    float sum  = 0.0f;
    float cntf = 0.0f;

#pragma unroll 3
    for (int j = 0; j < 30; ++j) {
        const float4 A  = buf[j & 1][0];
        const float4 Bv = buf[j & 1][1];
        const float4 C  = buf[j & 1][2];
        const float4* q = p + 192;             // distance-2 ahead
        buf[j & 1][0] = __ldcs(q + 0);
        buf[j & 1][1] = __ldcs(q + 1);
        buf[j & 1][2] = __ldcs(q + 2);
        p += 96;
        process4(A, Bv, C, r00, r01, r02, r10, r11, r12, r20, r21, r22,
                 trx, try_, trz, sum, cntf);
    }
    process4(buf[0][0], buf[0][1], buf[0][2], r00, r01, r02, r10, r11, r12,
             r20, r21, r22, trx, try_, trz, sum, cntf);
    process4(buf[1][0], buf[1][1], buf[1][2], r00, r01, r02, r10, r11, r12,
             r20, r21, r22, trx, try_, trz, sum, cntf);

    // ---- warp reduction (no smem, no barriers) ----
#pragma unroll
    for (int off = 16; off > 0; off >>= 1) {
        sum  += __shfl_down_sync(0xFFFFFFFFu, sum, off);
        cntf += __shfl_down_sync(0xFFFFFFFFu, cntf, off);
    }
    if (lane == 0) {
        const float dist = (cntf > 0.0f) ? (-sum / fmaxf(cntf, 1.0f)) : 1.0f;
        out[b] = dist * 10000.0f;
    }
}

extern "C" void kernel_launch(void* const* d_in, const int* in_sizes, int n_in,
                              void* d_out, int out_size)
{
    const float* trans = (const float*)d_in[0];  // [4096,3]
    const float* quat  = (const float*)d_in[1];  // [4096,4]
    const float* pc    = (const float*)d_in[2];  // [4096,4096,3]
    float* out = (float*)d_out;                  // [4096,1]

    const int B = in_sizes[0] / 3;               // 4096 poses
    collision_dist_kernel<<<B, 32>>>(trans, quat, pc, out);
}

// round 12
// speedup vs baseline: 1.4654x; 1.4654x over previous
#include <cuda_runtime.h>
#include <cstdint>

// B=4096 poses x N=4096 points, pure HBM streaming reduction (201 MB).
// R12 = R8 (best body: warp-per-pose, 4096 one-warp CTAs, cap 28 = single
// wave, dist-2 ring with UNROLL 2 (ring period!), rsqrt norm, ptr-increment)
// + float count accumulator (fma pipe instead of alu).
// R11 lesson: unroll factor must be a multiple of the ring period, else the
// buf[] index goes dynamic and ptxas spills the ring to local memory.

#define NPTS 4096

__device__ __forceinline__ void process4(
    const float4 A, const float4 Bv, const float4 C,
    const float r00, const float r01, const float r02,
    const float r10, const float r11, const float r12,
    const float r20, const float r21, const float r22,
    const float trx, const float try_, const float trz,
    float& sum, float& cntf)
{
    // AABB bounds (identical double->float rounding to the numpy reference)
    const float lox = (float)(-0.001782 - (0.204416 / 2.0 + 0.001));
    const float hix = (float)(-0.001782 + (0.204416 / 2.0 + 0.001));
    const float loy = (float)(1.005e-05 - (0.0632517 / 2.0 + 0.001));
    const float hiy = (float)(1.005e-05 + (0.0632517 / 2.0 + 0.001));
    const float loz = (float)(0.0431621 - (0.1381738 / 2.0 + 0.001));
    const float hiz = (float)(0.0431621 + (0.1381738 / 2.0 + 0.001));

    const float px[4] = {A.x, A.w, Bv.z, C.y};
    const float py[4] = {A.y, Bv.x, Bv.w, C.z};
    const float pz[4] = {A.z, Bv.y, C.x, C.w};
#pragma unroll
    for (int k = 0; k < 4; ++k) {
        const float x = px[k], y = py[k], z = pz[k];
        const float rx = fmaf(r00, x, fmaf(r01, y, fmaf(r02, z, -trx)));
        const float ry = fmaf(r10, x, fmaf(r11, y, fmaf(r12, z, -try_)));
        const float rz = fmaf(r20, x, fmaf(r21, y, fmaf(r22, z, -trz)));
        const bool inside =
            (rx >= lox) & (rx <= hix) &
            (ry >= loy) & (ry <= hiy) &
            (rz >= loz) & (rz <= hiz);
        const float r2 = fmaf(rx, rx, fmaf(ry, ry, rz * rz));
        const float nrm = r2 * rsqrtf(fmaxf(r2, 1e-12f));  // = sqrt(r2)
        sum  += inside ? nrm : 0.0f;    // FSEL + FADD (fma pipe)
        cntf += inside ? 1.0f : 0.0f;   // FSEL + FADD (fma pipe, exact <= 2^24)
    }
}

__global__ __launch_bounds__(32, 28) void collision_dist_kernel(
    const float* __restrict__ trans,   // [B,3]
    const float* __restrict__ quat,    // [B,4]
    const float* __restrict__ pc,      // [B,N,3]
    float* __restrict__ out)           // [B,1]
{
    const int lane = threadIdx.x;
    const int b    = blockIdx.x;       // one pose per warp/CTA

    // per-lane base pointer; advances by constant stride -> LDG [R+imm]
    const float4* p = reinterpret_cast<const float4*>(
        pc + (size_t)b * (size_t)NPTS * 3) + (size_t)lane * 3;

    // ---- prologue: 2 chunks (6 float4) in flight before dependent math ----
    float4 buf[2][3];
    buf[0][0] = __ldcs(p + 0);  buf[0][1] = __ldcs(p + 1);  buf[0][2] = __ldcs(p + 2);
    buf[1][0] = __ldcs(p + 96); buf[1][1] = __ldcs(p + 97); buf[1][2] = __ldcs(p + 98);

    // ---- per-pose setup overlaps the in-flight loads ----
    const float qx = __ldg(&quat[b * 4 + 0]);
    const float qy = __ldg(&quat[b * 4 + 1]);
    const float qz = __ldg(&quat[b * 4 + 2]);
    const float qw = __ldg(&quat[b * 4 + 3]);
    const float inv = 1.0f / (qx * qx + qy * qy + qz * qz + qw * qw);
    const float tx = -qx * inv, ty = -qy * inv, tz = -qz * inv, tw = qw * inv;

    const float txx = tx * tx, tyy = ty * ty, tzz = tz * tz, tww = tw * tw;
    const float r00 = tww + txx - tyy - tzz;
    const float r11 = tww - txx + tyy - tzz;
    const float r22 = tww - txx - tyy + tzz;
    const float r01 = 2.0f * (tx * ty - tw * tz);
    const float r02 = 2.0f * (tx * tz + tw * ty);
    const float r10 = 2.0f * (tx * ty + tw * tz);
    const float r12 = 2.0f * (ty * tz - tw * tx);
    const float r20 = 2.0f * (tx * tz - tw * ty);
    const float r21 = 2.0f * (ty * tz + tw * tx);

    const float trx  = __ldg(&trans[b * 3 + 0]);
    const float try_ = __ldg(&trans[b * 3 + 1]);
    const float trz  = __ldg(&trans[b * 3 + 2]);

    // ---- steady state: 32 chunks/lane, distance-2, pointer-increment ----
    float sum  = 0.0f;
    float cntf = 0.0f;

    // unroll 2 == ring period -> buf index is compile-time, stays in regs
#pragma unroll 2
    for (int j = 0; j < 30; ++j) {
        const float4 A  = buf[j & 1][0];
        const float4 Bv = buf[j & 1][1];
        const float4 C  = buf[j & 1][2];
        const float4* q = p + 192;             // distance-2 ahead
        buf[j & 1][0] = __ldcs(q + 0);
        buf[j & 1][1] = __ldcs(q + 1);
        buf[j & 1][2] = __ldcs(q + 2);
        p += 96;
        process4(A, Bv, C, r00, r01, r02, r10, r11, r12, r20, r21, r22,
                 trx, try_, trz, sum, cntf);
    }
    process4(buf[0][0], buf[0][1], buf[0][2], r00, r01, r02, r10, r11, r12,
             r20, r21, r22, trx, try_, trz, sum, cntf);
    process4(buf[1][0], buf[1][1], buf[1][2], r00, r01, r02, r10, r11, r12,
             r20, r21, r22, trx, try_, trz, sum, cntf);

    // ---- warp reduction (no smem, no barriers) ----
#pragma unroll
    for (int off = 16; off > 0; off >>= 1) {
        sum  += __shfl_down_sync(0xFFFFFFFFu, sum, off);
        cntf += __shfl_down_sync(0xFFFFFFFFu, cntf, off);
    }
    if (lane == 0) {
        const float dist = (cntf > 0.0f) ? (-sum / fmaxf(cntf, 1.0f)) : 1.0f;
        out[b] = dist * 10000.0f;
    }
}

extern "C" void kernel_launch(void* const* d_in, const int* in_sizes, int n_in,
                              void* d_out, int out_size)
{
    const float* trans = (const float*)d_in[0];  // [4096,3]
    const float* quat  = (const float*)d_in[1];  // [4096,4]
    const float* pc    = (const float*)d_in[2];  // [4096,4096,3]
    float* out = (float*)d_out;                  // [4096,1]

    const int B = in_sizes[0] / 3;               // 4096 poses
    collision_dist_kernel<<<B, 32>>>(trans, quat, pc, out);
}